// round 3
// baseline (speedup 1.0000x reference)
#include <cuda_runtime.h>

typedef unsigned long long ull;

#define B_DIM    128
#define IN_DIM   1024
#define OUT_DIM  1024
#define KSPLIT   16
#define K_SLICE  64
#define O_TILE   64
#define THREADS  256

// 8 MB fp32 partial sums: g_part[ks][b][o]
__device__ float g_part[KSPLIT * B_DIM * OUT_DIM];

__device__ __forceinline__ ull fma2(ull a, ull b, ull c) {
    ull d;
    asm("fma.rn.f32x2 %0, %1, %2, %3;" : "=l"(d) : "l"(a), "l"(b), "l"(c));
    return d;
}
__device__ __forceinline__ ull dup2(float w) {
    unsigned u = __float_as_uint(w);
    ull d;
    asm("mov.b64 %0, {%1, %1};" : "=l"(d) : "r"(u));
    return d;
}
__device__ __forceinline__ float lo32(ull v) { return __uint_as_float((unsigned)v); }
__device__ __forceinline__ float hi32(ull v) { return __uint_as_float((unsigned)(v >> 32)); }

// ---------------------------------------------------------------------------
// Kernel A: split-K GEMM with on-the-fly W gather.
//   grid (16,16): x = k-slice, y = o-tile. 256 threads.
//   Microtile: 8 batches x 4 outputs per thread (f32x2 over batch pairs).
// ---------------------------------------------------------------------------
__global__ void __launch_bounds__(THREADS)
sic_gemm(const float* __restrict__ x, const float* __restrict__ means,
         const int* __restrict__ dest)
{
    __shared__ __align__(16) float xs[K_SLICE * B_DIM];   // [kk][b], 16B-chunk swizzled
    __shared__ __align__(16) float ws[K_SLICE * O_TILE];  // [kk][o], 16B-chunk swizzled

    const int tid = threadIdx.x;
    const int k0  = blockIdx.x * K_SLICE;
    const int o0  = blockIdx.y * O_TILE;

    // ---- x slice -> smem, transposed + swizzled (swizzle kills bank conflicts
    //      on the kv-strided stores; reads recompute the same chunk XOR) ----
    for (int s = tid; s < B_DIM * (K_SLICE / 4); s += THREADS) {
        const int b  = s >> 4;
        const int kv = (s & 15) << 2;
        const float4 v = *reinterpret_cast<const float4*>(x + b * IN_DIM + k0 + kv);
        const int bc = b >> 2, bl = b & 3;
        xs[(kv + 0) * B_DIM + ((((bc ^ (kv + 0)) & 31) << 2) | bl)] = v.x;
        xs[(kv + 1) * B_DIM + ((((bc ^ (kv + 1)) & 31) << 2) | bl)] = v.y;
        xs[(kv + 2) * B_DIM + ((((bc ^ (kv + 2)) & 31) << 2) | bl)] = v.z;
        xs[(kv + 3) * B_DIM + ((((bc ^ (kv + 3)) & 31) << 2) | bl)] = v.w;
    }

    // ---- W tile gather: ws[kk][o] = means[dest[(o0+o)*IN + k0+kk]] ----
    for (int s = tid; s < O_TILE * (K_SLICE / 4); s += THREADS) {
        const int o  = s >> 4;
        const int kv = (s & 15) << 2;
        const int4 dd = *reinterpret_cast<const int4*>(dest + (size_t)(o0 + o) * IN_DIM + k0 + kv);
        const int oc = o >> 2, ol = o & 3;
        ws[(kv + 0) * O_TILE + ((((oc ^ (kv + 0)) & 15) << 2) | ol)] = means[dd.x];
        ws[(kv + 1) * O_TILE + ((((oc ^ (kv + 1)) & 15) << 2) | ol)] = means[dd.y];
        ws[(kv + 2) * O_TILE + ((((oc ^ (kv + 2)) & 15) << 2) | ol)] = means[dd.z];
        ws[(kv + 3) * O_TILE + ((((oc ^ (kv + 3)) & 15) << 2) | ol)] = means[dd.w];
    }
    __syncthreads();

    // Thread mapping: o varies fastest across lanes (coalesced epilogue, ws
    // reads conflict-free), b broadcast within half-warp (xs reads broadcast).
    const int o_base = (tid & 15) * 4;
    const int b_base = (tid >> 4) * 8;
    const int wc0 = o_base >> 2;   // == tid & 15
    const int xc0 = b_base >> 2;   // even, 0..30

    ull acc[16];   // acc[oi*4 + pair], pair p covers batches b_base+2p, +2p+1
#pragma unroll
    for (int i = 0; i < 16; i++) acc[i] = 0ull;

#pragma unroll 8
    for (int kk = 0; kk < K_SLICE; kk++) {
        const float* xrow = xs + kk * B_DIM;
        const ulonglong2 xa = *reinterpret_cast<const ulonglong2*>(
            xrow + ((( xc0      ^ kk) & 31) << 2));   // batches b_base..b_base+3
        const ulonglong2 xb = *reinterpret_cast<const ulonglong2*>(
            xrow + ((((xc0 + 1) ^ kk) & 31) << 2));   // batches b_base+4..+7
        const float4 wv = *reinterpret_cast<const float4*>(
            ws + kk * O_TILE + (((wc0 ^ kk) & 15) << 2));
        const ull w0 = dup2(wv.x), w1 = dup2(wv.y), w2 = dup2(wv.z), w3 = dup2(wv.w);
        acc[0]  = fma2(xa.x, w0, acc[0]);
        acc[1]  = fma2(xa.y, w0, acc[1]);
        acc[2]  = fma2(xb.x, w0, acc[2]);
        acc[3]  = fma2(xb.y, w0, acc[3]);
        acc[4]  = fma2(xa.x, w1, acc[4]);
        acc[5]  = fma2(xa.y, w1, acc[5]);
        acc[6]  = fma2(xb.x, w1, acc[6]);
        acc[7]  = fma2(xb.y, w1, acc[7]);
        acc[8]  = fma2(xa.x, w2, acc[8]);
        acc[9]  = fma2(xa.y, w2, acc[9]);
        acc[10] = fma2(xb.x, w2, acc[10]);
        acc[11] = fma2(xb.y, w2, acc[11]);
        acc[12] = fma2(xa.x, w3, acc[12]);
        acc[13] = fma2(xa.y, w3, acc[13]);
        acc[14] = fma2(xb.x, w3, acc[14]);
        acc[15] = fma2(xb.y, w3, acc[15]);
    }

    // ---- epilogue: repack so each store is a contiguous-o float4.
    //      16 lanes * 16B = 256B contiguous per b row -> fully coalesced. ----
    float* base = g_part + ((size_t)(blockIdx.x * B_DIM + b_base)) * OUT_DIM + o0 + o_base;
#pragma unroll
    for (int p = 0; p < 4; p++) {
        float4 vlo, vhi;
        vlo.x = lo32(acc[p]);      vhi.x = hi32(acc[p]);
        vlo.y = lo32(acc[4 + p]);  vhi.y = hi32(acc[4 + p]);
        vlo.z = lo32(acc[8 + p]);  vhi.z = hi32(acc[8 + p]);
        vlo.w = lo32(acc[12 + p]); vhi.w = hi32(acc[12 + p]);
        *reinterpret_cast<float4*>(base + (size_t)(2 * p)     * OUT_DIM) = vlo;
        *reinterpret_cast<float4*>(base + (size_t)(2 * p + 1) * OUT_DIM) = vhi;
    }
}

// ---------------------------------------------------------------------------
// Kernel B: fold 16 k-split partials + bias -> out. One float4 per thread.
// ---------------------------------------------------------------------------
__global__ void __launch_bounds__(THREADS)
sic_reduce(const float* __restrict__ bias, float* __restrict__ out)
{
    const int i   = blockIdx.x * THREADS + threadIdx.x;  // 0..32767
    const int off = i * 4;                               // b*1024 + o
    const int o   = off & (OUT_DIM - 1);

    float4 a = make_float4(0.f, 0.f, 0.f, 0.f);
#pragma unroll
    for (int ks = 0; ks < KSPLIT; ks++) {
        const float4 v = *reinterpret_cast<const float4*>(
            g_part + (size_t)ks * (B_DIM * OUT_DIM) + off);
        a.x += v.x; a.y += v.y; a.z += v.z; a.w += v.w;
    }
    const float4 bb = *reinterpret_cast<const float4*>(bias + o);
    a.x += bb.x; a.y += bb.y; a.z += bb.z; a.w += bb.w;
    *reinterpret_cast<float4*>(out + off) = a;
}

extern "C" void kernel_launch(void* const* d_in, const int* in_sizes, int n_in,
                              void* d_out, int out_size)
{
    (void)in_sizes; (void)n_in; (void)out_size;
    const float* x     = (const float*)d_in[0];   // [128,1024] f32
    const float* means = (const float*)d_in[1];   // [1024,16]  f32
    const float* bias  = (const float*)d_in[2];   // [1024]     f32
    // d_in[3] = col_idx (identity per row; unused)
    const int*   dest  = (const int*)d_in[4];     // [1024*1024] i32
    float* out = (float*)d_out;

    sic_gemm<<<dim3(KSPLIT, OUT_DIM / O_TILE), THREADS>>>(x, means, dest);
    sic_reduce<<<(B_DIM * OUT_DIM / 4) / THREADS, THREADS>>>(bias, out);
}